// round 14
// baseline (speedup 1.0000x reference)
#include <cuda_runtime.h>
#include <math.h>
#include <stdint.h>

#define BATCH 32
#define NPTS  512
#define NN    (BATCH*NPTS)     // 16384
#define ND    128
#define F0D   384
#define HROWS 513

// ---------------- scratch (device globals) ----------------
__device__ float g_L  [(size_t)BATCH*NPTS*NPTS];   // raw A
__device__ float g_U  [(size_t)NN*64];             // [M | LM | LLM | 0pad]
__device__ float g_Mt [(size_t)BATCH*20*NPTS];     // per batch [mono][point]
__device__ float g_LMt[(size_t)BATCH*20*NPTS];
__device__ float g_R  [(size_t)64*F0D];            // rows 60..63 zero
__device__ float g_F1 [(size_t)NN*F0D];
__device__ float g_deg[NN];
__device__ float g_ps [(size_t)128*F0D];           // BN partials per row-block
__device__ float g_pq [(size_t)128*F0D];
__device__ float g_scale[F0D];
__device__ float g_colbias[ND];
__device__ float g_os [(size_t)128*ND];            // fgemm per-block channel sums
__device__ unsigned g_dlmax_bits;                  // idempotent max (never reset)
__device__ unsigned g_amax_bits;

// ---------------- monomial helper (order: 1,x,y,z,x2,xy,xz,y2,yz,z2,x3,...) ----------------
__device__ __forceinline__ void monos(float x, float y, float z, float* m) {
    m[0]=1.0f; m[1]=x; m[2]=y; m[3]=z;
    m[4]=x*x; m[5]=x*y; m[6]=x*z; m[7]=y*y; m[8]=y*z; m[9]=z*z;
    m[10]=m[4]*x; m[11]=m[4]*y; m[12]=m[4]*z; m[13]=x*m[7]; m[14]=m[5]*z;
    m[15]=x*m[9]; m[16]=m[7]*y; m[17]=m[7]*z; m[18]=y*m[9]; m[19]=m[9]*z;
}

// ---------------- polynomial coefficient (power kb+1, monomial pm) ----------------
__device__ __forceinline__ float coefP(int kb, int pm, float a, float b, float c, float d) {
    if (kb == 0) {
        switch (pm) { case 0: return d; case 1: return a; case 2: return b; case 3: return c; }
        return 0.f;
    } else if (kb == 1) {
        switch (pm) {
            case 0: return d*d;     case 1: return 2.f*a*d; case 2: return 2.f*b*d;
            case 3: return 2.f*c*d; case 4: return a*a;     case 5: return 2.f*a*b;
            case 6: return 2.f*a*c; case 7: return b*b;     case 8: return 2.f*b*c;
            case 9: return c*c;
        }
        return 0.f;
    }
    switch (pm) {
        case 0:  return d*d*d;     case 1:  return 3.f*a*d*d; case 2:  return 3.f*b*d*d;
        case 3:  return 3.f*c*d*d; case 4:  return 3.f*a*a*d; case 5:  return 6.f*a*b*d;
        case 6:  return 6.f*a*c*d; case 7:  return 3.f*b*b*d; case 8:  return 6.f*b*c*d;
        case 9:  return 3.f*c*c*d; case 10: return a*a*a;     case 11: return 3.f*a*a*b;
        case 12: return 3.f*a*a*c; case 13: return 3.f*a*b*b; case 14: return 6.f*a*b*c;
        case 15: return 3.f*a*c*c; case 16: return b*b*b;     case 17: return 3.f*b*b*c;
        case 18: return 3.f*b*c*c; case 19: return c*c*c;
    }
    return 0.f;
}

// ---------------- pre_k: dlmax (blocks 0..63) + rbuild (blocks 64..255) ----------------
__global__ void __launch_bounds__(256) pre_k(
    const float* __restrict__ dl,
    const float* __restrict__ W1, const float* __restrict__ W2,
    const float* __restrict__ W3, const float* __restrict__ Wi,
    const float* __restrict__ bi)
{
    int bid = blockIdx.x, t = threadIdx.x;
    if (bid < 64) {
        __shared__ float red[8];
        float v = dl[bid*256 + t];
        #pragma unroll
        for (int o = 16; o; o >>= 1) v = fmaxf(v, __shfl_xor_sync(0xffffffff, v, o));
        if ((t & 31) == 0) red[t >> 5] = v;
        __syncthreads();
        if (t == 0) {
            float m = red[0];
            #pragma unroll
            for (int w = 1; w < 8; w++) m = fmaxf(m, red[w]);
            atomicMax(&g_dlmax_bits, __float_as_uint(m));
        }
        return;
    }
    int rb = bid - 64;               // 0..191
    int p  = rb & 63;                // 0..63
    int kb = rb >> 6;                // 0..2
    __shared__ float sa[F0D], sb[F0D], sc_[F0D], sd[F0D];
    for (int j = t; j < F0D; j += 256) {
        sa[j] = Wi[j]; sb[j] = Wi[F0D+j]; sc_[j] = Wi[2*F0D+j]; sd[j] = bi[j];
    }
    __syncthreads();
    if (t >= 128) return;
    int jj = t;
    if (p >= 60) { g_R[(size_t)p*F0D + kb*ND + jj] = 0.f; return; }
    int tt = p / 20, pm = p % 20;
    const float* Wg = ((kb == 0) ? W1 : (kb == 1 ? W2 : W3)) + (size_t)tt*F0D*ND + jj;
    float s0 = 0.f, s1 = 0.f, s2 = 0.f, s3 = 0.f;
    #pragma unroll 2
    for (int j = 0; j < F0D; j += 4) {
        s0 = fmaf(coefP(kb, pm, sa[j],   sb[j],   sc_[j],   sd[j]),   Wg[(size_t)j*ND],     s0);
        s1 = fmaf(coefP(kb, pm, sa[j+1], sb[j+1], sc_[j+1], sd[j+1]), Wg[(size_t)(j+1)*ND], s1);
        s2 = fmaf(coefP(kb, pm, sa[j+2], sb[j+2], sc_[j+2], sd[j+2]), Wg[(size_t)(j+2)*ND], s2);
        s3 = fmaf(coefP(kb, pm, sa[j+3], sb[j+3], sc_[j+3], sd[j+3]), Wg[(size_t)(j+3)*ND], s3);
    }
    g_R[(size_t)p*F0D + kb*ND + jj] = (s0 + s1) + (s2 + s3);
}

// ---------------- a_k: A tiles (upper-tri + transposed mirror) + X inline + monos on diagonal ----------------
__global__ void __launch_bounds__(256) a_k(const float* __restrict__ loc, const float* __restrict__ dl) {
    int ti = blockIdx.y, tj = blockIdx.x;
    if (ti > tj) return;
    int b  = blockIdx.z;
    int i0 = ti * 32, j0 = tj * 32;
    __shared__ float Xi[32][3], Xj[32][3];
    __shared__ float T[32][33];
    int t = threadIdx.x;
    float invd = 1.0f / __uint_as_float(g_dlmax_bits);
    if (t < 32) {
        int gp = b*NPTS + i0 + t;
        Xi[t][0] = loc[gp*2]; Xi[t][1] = loc[gp*2+1]; Xi[t][2] = dl[gp] * invd;
    } else if (t < 64) {
        int p = t - 32;
        int gp = b*NPTS + j0 + p;
        Xj[p][0] = loc[gp*2]; Xj[p][1] = loc[gp*2+1]; Xj[p][2] = dl[gp] * invd;
    }
    __syncthreads();
    int tx = t & 31, ty = t >> 5;
    float xj0 = Xj[tx][0], xj1 = Xj[tx][1], xj2 = Xj[tx][2];
    float m = 0.0f;
    float* Ab = g_L + (size_t)b * NPTS * NPTS;
    #pragma unroll
    for (int r = 0; r < 4; r++) {
        int i = ty * 4 + r;
        float dx = Xi[i][0]-xj0, dy = Xi[i][1]-xj1, dz = Xi[i][2]-xj2;
        float d2 = dx*dx + dy*dy + dz*dz;
        float v  = (i0 + i == j0 + tx) ? 0.0f : rsqrtf(d2);
        Ab[(size_t)(i0+i)*NPTS + j0 + tx] = v;
        T[i][tx] = v;
        m = fmaxf(m, v);
    }
    #pragma unroll
    for (int o = 16; o; o >>= 1) m = fmaxf(m, __shfl_xor_sync(0xffffffff, m, o));
    __shared__ float wm[8];
    if (tx == 0) wm[ty] = m;
    __syncthreads();
    if (ti < tj) {
        #pragma unroll
        for (int r = 0; r < 4; r++) {
            int ip = ty * 4 + r;
            Ab[(size_t)(j0+ip)*NPTS + i0 + tx] = T[tx][ip];   // transposed mirror
        }
    } else if (t < 32) {
        // diagonal block: monomials for its 32 points (each point exactly once)
        float mm[20];
        monos(Xj[t][0], Xj[t][1], Xj[t][2], mm);
        int gp = b*NPTS + j0 + t;
        float* u = g_U + (size_t)gp*64;
        #pragma unroll
        for (int p = 0; p < 20; p++) u[p] = mm[p];
        u[60]=0.f; u[61]=0.f; u[62]=0.f; u[63]=0.f;
        #pragma unroll
        for (int p = 0; p < 20; p++) g_Mt[(size_t)b*20*NPTS + p*NPTS + j0 + t] = mm[p];
    }
    if (t == 0) {
        float mx = wm[0];
        #pragma unroll
        for (int w = 1; w < 8; w++) mx = fmaxf(mx, wm[w]);
        atomicMax(&g_amax_bits, __float_as_uint(mx));
    }
}

// ---------------- L propagation from RAW A: 4-row register blocking ----------------
__global__ void __launch_bounds__(256) lprop_k(int mode) {
    __shared__ float Ms[20*NPTS];
    int b = blockIdx.y;
    const float* src = (mode ? g_LMt : g_Mt) + (size_t)b*20*NPTS;
    for (int i = threadIdx.x; i < 20*NPTS; i += 256) Ms[i] = src[i];
    __syncthreads();
    float inv = 1.0f / __uint_as_float(g_amax_bits);
    int wid = threadIdx.x >> 5, lane = threadIdx.x & 31;
    #pragma unroll 1
    for (int g = 0; g < 2; g++) {
        int il0 = blockIdx.x*64 + wid*8 + g*4;
        const float* A0 = g_L + ((size_t)b*NPTS + il0)*NPTS;
        float acc[4][20];
        float rs[4] = {0.f, 0.f, 0.f, 0.f};
        #pragma unroll
        for (int r = 0; r < 4; r++)
            #pragma unroll
            for (int c = 0; c < 20; c++) acc[r][c] = 0.f;
        #pragma unroll 2
        for (int t = 0; t < 16; t++) {
            int idx = lane + 32*t;
            float a0 = A0[idx];
            float a1 = A0[NPTS + idx];
            float a2 = A0[2*NPTS + idx];
            float a3 = A0[3*NPTS + idx];
            rs[0] += a0; rs[1] += a1; rs[2] += a2; rs[3] += a3;
            #pragma unroll
            for (int c = 0; c < 20; c++) {
                float ms = Ms[c*NPTS + idx];
                acc[0][c] = fmaf(a0, ms, acc[0][c]);
                acc[1][c] = fmaf(a1, ms, acc[1][c]);
                acc[2][c] = fmaf(a2, ms, acc[2][c]);
                acc[3][c] = fmaf(a3, ms, acc[3][c]);
            }
        }
        #pragma unroll
        for (int r = 0; r < 4; r++) {
            #pragma unroll
            for (int o = 16; o; o >>= 1) rs[r] += __shfl_xor_sync(0xffffffff, rs[r], o);
            #pragma unroll
            for (int c = 0; c < 20; c++) {
                float v = acc[r][c];
                #pragma unroll
                for (int o = 16; o; o >>= 1) v += __shfl_xor_sync(0xffffffff, v, o);
                acc[r][c] = v;
            }
        }
        if (lane < 4) {
            int il = il0 + lane;
            float rsv = (lane == 0) ? rs[0] : (lane == 1) ? rs[1] : (lane == 2) ? rs[2] : rs[3];
            float deg;
            if (!mode) { deg = rsv * inv - 1.0f; g_deg[(size_t)b*NPTS + il] = deg; }
            else        deg = g_deg[(size_t)b*NPTS + il];
            float* u = g_U + ((size_t)b*NPTS + il)*64 + (mode ? 40 : 20);
            #pragma unroll
            for (int c = 0; c < 20; c++) {
                float av = (lane == 0) ? acc[0][c] : (lane == 1) ? acc[1][c]
                         : (lane == 2) ? acc[2][c] : acc[3][c];
                float o = deg * Ms[c*NPTS + il] - av * inv;
                u[c] = o;
                if (!mode) g_LMt[(size_t)b*20*NPTS + c*NPTS + il] = o;
            }
        }
    }
}

// ---------------- F1 = leaky(U@R + bg) + F0(inline) ; epilogue: BN partials ----------------
__global__ void __launch_bounds__(256) f1gemm_k(
    const float* __restrict__ bg1, const float* __restrict__ bg2, const float* __restrict__ bg3,
    const float* __restrict__ Wi,  const float* __restrict__ bi,
    const float* __restrict__ loc, const float* __restrict__ dl)
{
    int bm = blockIdx.x * 128;
    int kb = blockIdx.y;
    const float* bg = (kb == 0) ? bg1 : (kb == 1 ? bg2 : bg3);
    __shared__ float As[8][128], Bs[8][128];
    __shared__ float sWa[128], sWb[128], sWc[128], sbi[128], sx[128], sy[128], sz[128];
    __shared__ float redS[16][128], redQ[16][128];
    int t = threadIdx.x;
    if (t < 128) {
        int c = kb*128 + t;
        sWa[t] = Wi[c]; sWb[t] = Wi[F0D+c]; sWc[t] = Wi[2*F0D+c]; sbi[t] = bi[c];
        int r = bm + t;
        float invd = 1.0f / __uint_as_float(g_dlmax_bits);
        sx[t] = loc[r*2]; sy[t] = loc[r*2+1]; sz[t] = dl[r] * invd;
    }
    int arow = t >> 1, acol = (t & 1) * 4;
    int brow = t >> 5, bcol = (t & 31) * 4;
    int tx = t & 15, ty = t >> 4;
    float acc[8][8] = {};
    const float* Aptr = g_U + (size_t)(bm + arow) * 64 + acol;
    const float* Bptr = g_R + (size_t)brow * F0D + kb * ND + bcol;
    __syncthreads();
    for (int k0 = 0; k0 < 64; k0 += 8) {
        float4 av = *(const float4*)(Aptr + k0);
        float4 bv = *(const float4*)(Bptr + (size_t)k0 * F0D);
        As[acol+0][arow] = av.x; As[acol+1][arow] = av.y;
        As[acol+2][arow] = av.z; As[acol+3][arow] = av.w;
        *(float4*)&Bs[brow][bcol] = bv;
        __syncthreads();
        #pragma unroll
        for (int kk = 0; kk < 8; kk++) {
            float ra[8], rb[8];
            *(float4*)(ra)   = *(float4*)&As[kk][ty*4];
            *(float4*)(ra+4) = *(float4*)&As[kk][64 + ty*4];
            *(float4*)(rb)   = *(float4*)&Bs[kk][tx*4];
            *(float4*)(rb+4) = *(float4*)&Bs[kk][64 + tx*4];
            #pragma unroll
            for (int i = 0; i < 8; i++)
                #pragma unroll
                for (int j = 0; j < 8; j++) acc[i][j] = fmaf(ra[i], rb[j], acc[i][j]);
        }
        __syncthreads();
    }
    float cS[8] = {}, cQ[8] = {};
    #pragma unroll
    for (int i = 0; i < 8; i++) {
        int rloc = (i < 4) ? ty*4 + i : 64 + ty*4 + (i-4);
        int r = bm + rloc;
        #pragma unroll
        for (int jj = 0; jj < 8; jj++) {
            int cloc = (jj < 4) ? tx*4 + jj : 64 + tx*4 + (jj-4);
            float v = acc[i][jj] + bg[cloc];
            v = (v > 0.0f) ? v : 0.01f * v;
            v += fmaf(sx[rloc], sWa[cloc],
                 fmaf(sy[rloc], sWb[cloc],
                 fmaf(sz[rloc], sWc[cloc], sbi[cloc])));
            g_F1[(size_t)r * F0D + kb * ND + cloc] = v;
            cS[jj] += v; cQ[jj] += v * v;
        }
    }
    #pragma unroll
    for (int jj = 0; jj < 8; jj++) {
        int cloc = (jj < 4) ? tx*4 + jj : 64 + tx*4 + (jj-4);
        redS[ty][cloc] = cS[jj]; redQ[ty][cloc] = cQ[jj];
    }
    __syncthreads();
    if (t < 128) {
        float s = 0.f, q = 0.f;
        #pragma unroll
        for (int g = 0; g < 16; g++) { s += redS[g][t]; q += redQ[g][t]; }
        g_ps[(size_t)blockIdx.x * F0D + kb * ND + t] = s;
        g_pq[(size_t)blockIdx.x * F0D + kb * ND + t] = q;
    }
}

// ---------------- BN finalize (one small kernel): scale, shift->colbias ----------------
__global__ void bnfin_k(const float* __restrict__ gamma, const float* __restrict__ beta,
                        const float* __restrict__ WF,    const float* __restrict__ bF) {
    __shared__ float sh[F0D];
    int t = threadIdx.x;                                   // 384 threads
    float s0=0.f, s1=0.f, q0=0.f, q1=0.f;
    #pragma unroll 4
    for (int rb = 0; rb < 128; rb += 2) {
        s0 += g_ps[(size_t)rb*F0D + t];     q0 += g_pq[(size_t)rb*F0D + t];
        s1 += g_ps[(size_t)(rb+1)*F0D + t]; q1 += g_pq[(size_t)(rb+1)*F0D + t];
    }
    float s = s0 + s1, q = q0 + q1;
    float mu  = s * (1.0f / NN);
    float var = q * (1.0f / NN) - mu * mu;
    float sc  = gamma[t] * rsqrtf(var + 1e-5f);
    g_scale[t] = sc;
    sh[t] = beta[t] - mu * sc;
    __syncthreads();
    if (t < ND) {
        float a0 = bF[t], a1 = 0.f, a2 = 0.f, a3 = 0.f;
        #pragma unroll 2
        for (int k = 0; k < F0D; k += 4) {
            a0 = fmaf(sh[k],   WF[(size_t)k*ND + t],     a0);
            a1 = fmaf(sh[k+1], WF[(size_t)(k+1)*ND + t], a1);
            a2 = fmaf(sh[k+2], WF[(size_t)(k+2)*ND + t], a2);
            a3 = fmaf(sh[k+3], WF[(size_t)(k+3)*ND + t], a3);
        }
        g_colbias[t] = (a0 + a1) + (a2 + a3);
    }
}

// ---------------- final GEMM (light prologue) + per-block channel sums ----------------
__global__ void __launch_bounds__(256) fgemm_k(const float* __restrict__ WF, float* __restrict__ out) {
    __shared__ float As[8][128], Bs[8][128];
    __shared__ float sSC[F0D], sCB[ND];
    __shared__ float redS[16][128];
    int t = threadIdx.x;
    for (int c = t; c < F0D; c += 256) sSC[c] = g_scale[c];
    if (t < ND) sCB[t] = g_colbias[t];
    __syncthreads();

    int bm = blockIdx.x * 128;
    int arow = t >> 1, acol = (t & 1) * 4;
    int brow = t >> 5, bcol = (t & 31) * 4;
    int tx = t & 15, ty = t >> 4;
    float acc[8][8] = {};
    const float* Aptr = g_F1 + (size_t)(bm + arow) * F0D + acol;
    for (int k0 = 0; k0 < F0D; k0 += 8) {
        float4 av = *(const float4*)(Aptr + k0);
        float4 sc = *(const float4*)&sSC[k0 + acol];
        av.x *= sc.x; av.y *= sc.y; av.z *= sc.z; av.w *= sc.w;
        float4 bv = *(const float4*)(WF + (size_t)(k0 + brow) * ND + bcol);
        As[acol+0][arow] = av.x; As[acol+1][arow] = av.y;
        As[acol+2][arow] = av.z; As[acol+3][arow] = av.w;
        *(float4*)&Bs[brow][bcol] = bv;
        __syncthreads();
        #pragma unroll
        for (int kk = 0; kk < 8; kk++) {
            float ra[8], rb[8];
            *(float4*)(ra)   = *(float4*)&As[kk][ty*4];
            *(float4*)(ra+4) = *(float4*)&As[kk][64 + ty*4];
            *(float4*)(rb)   = *(float4*)&Bs[kk][tx*4];
            *(float4*)(rb+4) = *(float4*)&Bs[kk][64 + tx*4];
            #pragma unroll
            for (int i = 0; i < 8; i++)
                #pragma unroll
                for (int j = 0; j < 8; j++) acc[i][j] = fmaf(ra[i], rb[j], acc[i][j]);
        }
        __syncthreads();
    }
    float cS[8] = {};
    #pragma unroll
    for (int i = 0; i < 8; i++) {
        int r    = bm + ((i < 4) ? ty*4 + i : 64 + ty*4 + (i-4));
        int b    = r >> 9;
        int nloc = r & 511;
        float* orow = out + ((size_t)b * HROWS + 1 + nloc) * ND;
        float v4[8];
        #pragma unroll
        for (int jj = 0; jj < 8; jj++) {
            int c = (jj < 4) ? tx*4 + jj : 64 + tx*4 + (jj-4);
            float v = acc[i][jj] + sCB[c];
            v = (v > 0.0f) ? v : 0.01f * v;
            v4[jj] = v;
            cS[jj] += v;
        }
        *(float4*)(orow + tx*4)      = *(float4*)&v4[0];
        *(float4*)(orow + 64 + tx*4) = *(float4*)&v4[4];
    }
    #pragma unroll
    for (int jj = 0; jj < 8; jj++) {
        int cloc = (jj < 4) ? tx*4 + jj : 64 + tx*4 + (jj-4);
        redS[ty][cloc] = cS[jj];
    }
    __syncthreads();
    if (t < 128) {
        float s = 0.f;
        #pragma unroll
        for (int g = 0; g < 16; g++) s += redS[g][t];
        g_os[(size_t)blockIdx.x * ND + t] = s;
    }
}

// ---------------- depot row + per-batch mean from partials ----------------
__global__ void depmean_k(const float* __restrict__ depot, const float* __restrict__ Wd,
                          const float* __restrict__ bd, float* __restrict__ out) {
    int b = blockIdx.x, t = threadIdx.x;                   // 32 x 128
    float v = fmaf(depot[b*2+0], Wd[t], fmaf(depot[b*2+1], Wd[ND + t], bd[t]));
    out[(size_t)b * HROWS * ND + t] = v;
    float tot = v + g_os[(size_t)(4*b)*ND + t]   + g_os[(size_t)(4*b+1)*ND + t]
                  + g_os[(size_t)(4*b+2)*ND + t] + g_os[(size_t)(4*b+3)*ND + t];
    out[(size_t)BATCH * HROWS * ND + (size_t)b * ND + t] = tot * (1.0f / HROWS);
}

// ---------------- launch (8 nodes) ----------------
extern "C" void kernel_launch(void* const* d_in, const int* in_sizes, int n_in,
                              void* d_out, int out_size) {
    const float* loc   = (const float*)d_in[0];
    const float* dl    = (const float*)d_in[1];
    const float* depot = (const float*)d_in[3];
    const float* Wi    = (const float*)d_in[4];
    const float* bi    = (const float*)d_in[5];
    const float* Wd    = (const float*)d_in[6];
    const float* bd    = (const float*)d_in[7];
    const float* Wg1   = (const float*)d_in[8];
    const float* bg1   = (const float*)d_in[9];
    const float* Wg2   = (const float*)d_in[10];
    const float* bg2   = (const float*)d_in[11];
    const float* Wg3   = (const float*)d_in[12];
    const float* bg3   = (const float*)d_in[13];
    const float* gamma = (const float*)d_in[14];
    const float* beta  = (const float*)d_in[15];
    const float* WF    = (const float*)d_in[16];
    const float* bF    = (const float*)d_in[17];
    float* out = (float*)d_out;

    pre_k    <<<256, 256>>>(dl, Wg1, Wg2, Wg3, Wi, bi);
    a_k      <<<dim3(16, 16, BATCH), 256>>>(loc, dl);
    lprop_k  <<<dim3(8, BATCH), 256>>>(0);
    lprop_k  <<<dim3(8, BATCH), 256>>>(1);
    f1gemm_k <<<dim3(NN/128, 3), 256>>>(bg1, bg2, bg3, Wi, bi, loc, dl);
    bnfin_k  <<<1, F0D>>>(gamma, beta, WF, bF);
    fgemm_k  <<<NN/128, 256>>>(WF, out);
    depmean_k<<<BATCH, ND>>>(depot, Wd, bd, out);
}

// round 15
// speedup vs baseline: 1.0304x; 1.0304x over previous
#include <cuda_runtime.h>
#include <math.h>
#include <stdint.h>

#define BATCH 32
#define NPTS  512
#define NN    (BATCH*NPTS)     // 16384
#define ND    128
#define F0D   384
#define HROWS 513

// ---------------- scratch (device globals) ----------------
__device__ float g_L  [(size_t)BATCH*NPTS*NPTS];   // raw A
__device__ float g_U  [(size_t)NN*64];             // [M | LM | LLM | 0pad]
__device__ float g_Mt [(size_t)BATCH*20*NPTS];     // per batch [mono][point]
__device__ float g_LMt[(size_t)BATCH*20*NPTS];
__device__ float g_R  [(size_t)64*F0D];            // rows 60..63 zero
__device__ float g_F1 [(size_t)NN*F0D];
__device__ float g_X  [NN*3];
__device__ float g_deg[NN];
__device__ float g_ps [(size_t)128*F0D];           // BN partials per row-block
__device__ float g_pq [(size_t)128*F0D];
__device__ float g_os [(size_t)128*ND];            // fgemm per-block channel sums
__device__ unsigned g_dlmax_bits;
__device__ unsigned g_amax_bits;

// ---------------- small kernels (R12-proven) ----------------
__global__ void init_k() {
    if (threadIdx.x == 0) { g_dlmax_bits = 0u; g_amax_bits = 0u; }
}
__global__ void dlmax_k(const float* __restrict__ dl) {
    int i = blockIdx.x * blockDim.x + threadIdx.x;
    float v = dl[i];
    #pragma unroll
    for (int o = 16; o; o >>= 1) v = fmaxf(v, __shfl_xor_sync(0xffffffff, v, o));
    if ((threadIdx.x & 31) == 0) atomicMax(&g_dlmax_bits, __float_as_uint(v));
}
__global__ void mono_k(const float* __restrict__ loc, const float* __restrict__ dl) {
    int i = blockIdx.x * blockDim.x + threadIdx.x;
    if (i >= NN) return;
    float inv = 1.0f / __uint_as_float(g_dlmax_bits);
    float x = loc[i*2+0], y = loc[i*2+1], z = dl[i] * inv;
    g_X[i*3+0] = x; g_X[i*3+1] = y; g_X[i*3+2] = z;
    float m[20];
    m[0]=1.0f; m[1]=x; m[2]=y; m[3]=z;
    m[4]=x*x; m[5]=x*y; m[6]=x*z; m[7]=y*y; m[8]=y*z; m[9]=z*z;
    m[10]=m[4]*x; m[11]=m[4]*y; m[12]=m[4]*z; m[13]=x*m[7]; m[14]=m[5]*z;
    m[15]=x*m[9]; m[16]=m[7]*y; m[17]=m[7]*z; m[18]=y*m[9]; m[19]=m[9]*z;
    float* u = g_U + (size_t)i*64;
    #pragma unroll
    for (int p = 0; p < 20; p++) u[p] = m[p];
    u[60]=0.f; u[61]=0.f; u[62]=0.f; u[63]=0.f;
    int b = i >> 9, nl = i & 511;
    #pragma unroll
    for (int p = 0; p < 20; p++) g_Mt[(size_t)b*20*NPTS + p*NPTS + nl] = m[p];
}
__global__ void a_k() {
    int ti = blockIdx.y, tj = blockIdx.x;
    if (ti > tj) return;
    int b  = blockIdx.z;
    int i0 = ti * 32, j0 = tj * 32;
    __shared__ float Xi[32][3], Xj[32][3];
    __shared__ float T[32][33];
    int t = threadIdx.x;
    if (t < 96)       ((float*)Xi)[t]    = g_X[((size_t)b*NPTS + i0)*3 + t];
    else if (t < 192) ((float*)Xj)[t-96] = g_X[((size_t)b*NPTS + j0)*3 + (t-96)];
    __syncthreads();
    int tx = t & 31, ty = t >> 5;
    float xj0 = Xj[tx][0], xj1 = Xj[tx][1], xj2 = Xj[tx][2];
    float m = 0.0f;
    float* Ab = g_L + (size_t)b * NPTS * NPTS;
    #pragma unroll
    for (int r = 0; r < 4; r++) {
        int i = ty * 4 + r;
        float dx = Xi[i][0]-xj0, dy = Xi[i][1]-xj1, dz = Xi[i][2]-xj2;
        float d2 = dx*dx + dy*dy + dz*dz;
        float v  = (i0 + i == j0 + tx) ? 0.0f : rsqrtf(d2);
        Ab[(size_t)(i0+i)*NPTS + j0 + tx] = v;
        T[i][tx] = v;
        m = fmaxf(m, v);
    }
    #pragma unroll
    for (int o = 16; o; o >>= 1) m = fmaxf(m, __shfl_xor_sync(0xffffffff, m, o));
    __shared__ float wm[8];
    if (tx == 0) wm[ty] = m;
    __syncthreads();
    if (ti < tj) {
        #pragma unroll
        for (int r = 0; r < 4; r++) {
            int ip = ty * 4 + r;
            Ab[(size_t)(j0+ip)*NPTS + i0 + tx] = T[tx][ip];   // transposed mirror
        }
    }
    if (t == 0) {
        float mx = wm[0];
        #pragma unroll
        for (int w = 1; w < 8; w++) mx = fmaxf(mx, wm[w]);
        atomicMax(&g_amax_bits, __float_as_uint(mx));
    }
}

// ---------------- polynomial coefficient (power kb+1, monomial pm) ----------------
__device__ __forceinline__ float coefP(int kb, int pm, float a, float b, float c, float d) {
    if (kb == 0) {
        switch (pm) { case 0: return d; case 1: return a; case 2: return b; case 3: return c; }
        return 0.f;
    } else if (kb == 1) {
        switch (pm) {
            case 0: return d*d;     case 1: return 2.f*a*d; case 2: return 2.f*b*d;
            case 3: return 2.f*c*d; case 4: return a*a;     case 5: return 2.f*a*b;
            case 6: return 2.f*a*c; case 7: return b*b;     case 8: return 2.f*b*c;
            case 9: return c*c;
        }
        return 0.f;
    }
    switch (pm) {
        case 0:  return d*d*d;     case 1:  return 3.f*a*d*d; case 2:  return 3.f*b*d*d;
        case 3:  return 3.f*c*d*d; case 4:  return 3.f*a*a*d; case 5:  return 6.f*a*b*d;
        case 6:  return 6.f*a*c*d; case 7:  return 3.f*b*b*d; case 8:  return 6.f*b*c*d;
        case 9:  return 3.f*c*c*d; case 10: return a*a*a;     case 11: return 3.f*a*a*b;
        case 12: return 3.f*a*a*c; case 13: return 3.f*a*b*b; case 14: return 6.f*a*b*c;
        case 15: return 3.f*a*c*c; case 16: return b*b*b;     case 17: return 3.f*b*b*c;
        case 18: return 3.f*b*c*c; case 19: return c*c*c;
    }
    return 0.f;
}

__global__ void rbuild_k(const float* __restrict__ W1, const float* __restrict__ W2,
                         const float* __restrict__ W3, const float* __restrict__ Wi,
                         const float* __restrict__ bi) {
    int p  = blockIdx.x;           // 0..63
    int kb = blockIdx.y;           // 0..2
    int jj = threadIdx.x;          // 0..127
    if (p >= 60) { g_R[(size_t)p*F0D + kb*ND + jj] = 0.f; return; }
    __shared__ float sa[F0D], sb[F0D], sc_[F0D], sd[F0D];
    for (int j = jj; j < F0D; j += 128) {
        sa[j] = Wi[j]; sb[j] = Wi[F0D+j]; sc_[j] = Wi[2*F0D+j]; sd[j] = bi[j];
    }
    __syncthreads();
    int t = p / 20, pm = p % 20;
    const float* Wg = ((kb == 0) ? W1 : (kb == 1 ? W2 : W3)) + (size_t)t*F0D*ND + jj;
    float s0 = 0.f, s1 = 0.f, s2 = 0.f, s3 = 0.f;
    #pragma unroll 2
    for (int j = 0; j < F0D; j += 4) {
        s0 = fmaf(coefP(kb, pm, sa[j],   sb[j],   sc_[j],   sd[j]),   Wg[(size_t)j*ND],     s0);
        s1 = fmaf(coefP(kb, pm, sa[j+1], sb[j+1], sc_[j+1], sd[j+1]), Wg[(size_t)(j+1)*ND], s1);
        s2 = fmaf(coefP(kb, pm, sa[j+2], sb[j+2], sc_[j+2], sd[j+2]), Wg[(size_t)(j+2)*ND], s2);
        s3 = fmaf(coefP(kb, pm, sa[j+3], sb[j+3], sc_[j+3], sd[j+3]), Wg[(size_t)(j+3)*ND], s3);
    }
    g_R[(size_t)p*F0D + kb*ND + jj] = (s0 + s1) + (s2 + s3);
}

// ---------------- NEW lprop: tiled GEMM C[512x20] = A @ Ms per batch ----------------
// grid (4, BATCH), 256 thr; block = 128 rows. Thread owns rows (rp, rp+64) x 5 cols.
// smem: Mst[512][21] (transposed, broadcast reads) + As[128][33] (k-tile).
#define LPSM_FLOATS (512*21 + 128*33)    // 14976 floats = 59904 B

__global__ void __launch_bounds__(256) lprop_k(int mode) {
    extern __shared__ float sm[];
    float* Mst = sm;                 // [k][c] padded to 21
    float* As  = sm + 512*21;        // [row][k] padded to 33
    int b = blockIdx.y, t = threadIdx.x;
    const float* src = (mode ? g_LMt : g_Mt) + (size_t)b*20*NPTS;
    for (int idx = t; idx < 20*NPTS; idx += 256) {
        int c = idx >> 9, k = idx & 511;
        Mst[k*21 + c] = src[idx];
    }
    __syncthreads();
    float inv = 1.0f / __uint_as_float(g_amax_bits);
    int rp = t & 63, cg = t >> 6;
    int c0 = cg * 5;
    int rb0 = blockIdx.x * 128;
    const float* A = g_L + ((size_t)b*NPTS + rb0)*NPTS;
    float acc0[5] = {}, acc1[5] = {};
    float rs0 = 0.f, rs1 = 0.f;
    #pragma unroll 1
    for (int kt = 0; kt < 16; kt++) {
        #pragma unroll
        for (int i = 0; i < 4; i++) {
            int fl = t + i*256;
            int row = fl >> 3, k4 = (fl & 7) * 4;
            float4 v = *(const float4*)(A + (size_t)row*NPTS + kt*32 + k4);
            float* d = As + row*33 + k4;
            d[0]=v.x; d[1]=v.y; d[2]=v.z; d[3]=v.w;
        }
        __syncthreads();
        #pragma unroll 4
        for (int kk = 0; kk < 32; kk++) {
            float a0 = As[rp*33 + kk];
            float a1 = As[(rp+64)*33 + kk];
            rs0 += a0; rs1 += a1;
            const float* mp = Mst + (kt*32 + kk)*21 + c0;
            #pragma unroll
            for (int j = 0; j < 5; j++) {
                float mv = mp[j];
                acc0[j] = fmaf(a0, mv, acc0[j]);
                acc1[j] = fmaf(a1, mv, acc1[j]);
            }
        }
        __syncthreads();
    }
    int grow0 = b*NPTS + rb0 + rp;
    int grow1 = grow0 + 64;
    float deg0, deg1;
    if (!mode) {
        deg0 = rs0 * inv - 1.0f;
        deg1 = rs1 * inv - 1.0f;
        if (cg == 0) { g_deg[grow0] = deg0; g_deg[grow1] = deg1; }
    } else {
        deg0 = g_deg[grow0]; deg1 = g_deg[grow1];
    }
    int off = mode ? 40 : 20;
    #pragma unroll
    for (int j = 0; j < 5; j++) {
        int c = c0 + j;
        float o0 = deg0 * Mst[(rb0+rp)*21 + c]    - acc0[j] * inv;
        float o1 = deg1 * Mst[(rb0+rp+64)*21 + c] - acc1[j] * inv;
        g_U[(size_t)grow0*64 + off + c] = o0;
        g_U[(size_t)grow1*64 + off + c] = o1;
        if (!mode) {
            g_LMt[(size_t)b*20*NPTS + (size_t)c*NPTS + rb0 + rp]      = o0;
            g_LMt[(size_t)b*20*NPTS + (size_t)c*NPTS + rb0 + rp + 64] = o1;
        }
    }
}

// ---------------- F1 = leaky(U@R + bg) + F0(inline) ; epilogue: BN partials ----------------
__global__ void __launch_bounds__(256) f1gemm_k(
    const float* __restrict__ bg1, const float* __restrict__ bg2, const float* __restrict__ bg3,
    const float* __restrict__ Wi,  const float* __restrict__ bi)
{
    int bm = blockIdx.x * 128;
    int kb = blockIdx.y;
    const float* bg = (kb == 0) ? bg1 : (kb == 1 ? bg2 : bg3);
    __shared__ float As[8][128], Bs[8][128];
    __shared__ float sWa[128], sWb[128], sWc[128], sbi[128], sx[128], sy[128], sz[128];
    __shared__ float redS[16][128], redQ[16][128];
    int t = threadIdx.x;
    if (t < 128) {
        int c = kb*128 + t;
        sWa[t] = Wi[c]; sWb[t] = Wi[F0D+c]; sWc[t] = Wi[2*F0D+c]; sbi[t] = bi[c];
        int r = bm + t;
        sx[t] = g_X[(size_t)r*3]; sy[t] = g_X[(size_t)r*3+1]; sz[t] = g_X[(size_t)r*3+2];
    }
    int arow = t >> 1, acol = (t & 1) * 4;
    int brow = t >> 5, bcol = (t & 31) * 4;
    int tx = t & 15, ty = t >> 4;
    float acc[8][8] = {};
    const float* Aptr = g_U + (size_t)(bm + arow) * 64 + acol;
    const float* Bptr = g_R + (size_t)brow * F0D + kb * ND + bcol;
    __syncthreads();
    for (int k0 = 0; k0 < 64; k0 += 8) {
        float4 av = *(const float4*)(Aptr + k0);
        float4 bv = *(const float4*)(Bptr + (size_t)k0 * F0D);
        As[acol+0][arow] = av.x; As[acol+1][arow] = av.y;
        As[acol+2][arow] = av.z; As[acol+3][arow] = av.w;
        *(float4*)&Bs[brow][bcol] = bv;
        __syncthreads();
        #pragma unroll
        for (int kk = 0; kk < 8; kk++) {
            float ra[8], rb[8];
            *(float4*)(ra)   = *(float4*)&As[kk][ty*4];
            *(float4*)(ra+4) = *(float4*)&As[kk][64 + ty*4];
            *(float4*)(rb)   = *(float4*)&Bs[kk][tx*4];
            *(float4*)(rb+4) = *(float4*)&Bs[kk][64 + tx*4];
            #pragma unroll
            for (int i = 0; i < 8; i++)
                #pragma unroll
                for (int j = 0; j < 8; j++) acc[i][j] = fmaf(ra[i], rb[j], acc[i][j]);
        }
        __syncthreads();
    }
    float cS[8] = {}, cQ[8] = {};
    #pragma unroll
    for (int i = 0; i < 8; i++) {
        int rloc = (i < 4) ? ty*4 + i : 64 + ty*4 + (i-4);
        int r = bm + rloc;
        #pragma unroll
        for (int jj = 0; jj < 8; jj++) {
            int cloc = (jj < 4) ? tx*4 + jj : 64 + tx*4 + (jj-4);
            float v = acc[i][jj] + bg[cloc];
            v = (v > 0.0f) ? v : 0.01f * v;
            v += fmaf(sx[rloc], sWa[cloc],
                 fmaf(sy[rloc], sWb[cloc],
                 fmaf(sz[rloc], sWc[cloc], sbi[cloc])));
            g_F1[(size_t)r * F0D + kb * ND + cloc] = v;
            cS[jj] += v; cQ[jj] += v * v;
        }
    }
    #pragma unroll
    for (int jj = 0; jj < 8; jj++) {
        int cloc = (jj < 4) ? tx*4 + jj : 64 + tx*4 + (jj-4);
        redS[ty][cloc] = cS[jj]; redQ[ty][cloc] = cQ[jj];
    }
    __syncthreads();
    if (t < 128) {
        float s = 0.f, q = 0.f;
        #pragma unroll
        for (int g = 0; g < 16; g++) { s += redS[g][t]; q += redQ[g][t]; }
        g_ps[(size_t)blockIdx.x * F0D + kb * ND + t] = s;
        g_pq[(size_t)blockIdx.x * F0D + kb * ND + t] = q;
    }
}

// ---------------- final GEMM: BN finalize in prologue (R12-style) + g_os epilogue ----------------
__global__ void __launch_bounds__(256) fgemm_k(
    const float* __restrict__ WF, const float* __restrict__ bF,
    const float* __restrict__ gamma, const float* __restrict__ beta,
    float* __restrict__ out)
{
    __shared__ float As[8][128], Bs[8][128];
    __shared__ float sSC[F0D], sSh[F0D], sCB[ND];
    __shared__ float redS[16][128];
    int t = threadIdx.x;
    for (int c = t; c < F0D; c += 256) {
        float s0=0.f, s1=0.f, q0=0.f, q1=0.f;
        #pragma unroll 4
        for (int rb = 0; rb < 128; rb += 2) {
            s0 += g_ps[(size_t)rb*F0D + c];     q0 += g_pq[(size_t)rb*F0D + c];
            s1 += g_ps[(size_t)(rb+1)*F0D + c]; q1 += g_pq[(size_t)(rb+1)*F0D + c];
        }
        float s = s0 + s1, q = q0 + q1;
        float mu  = s * (1.0f / NN);
        float var = q * (1.0f / NN) - mu * mu;
        float sc  = gamma[c] * rsqrtf(var + 1e-5f);
        sSC[c] = sc; sSh[c] = beta[c] - mu * sc;
    }
    __syncthreads();
    if (t < ND) {
        float s0 = bF[t], s1 = 0.f, s2 = 0.f, s3 = 0.f;
        #pragma unroll 2
        for (int k = 0; k < F0D; k += 4) {
            s0 = fmaf(sSh[k],   WF[(size_t)k*ND + t],     s0);
            s1 = fmaf(sSh[k+1], WF[(size_t)(k+1)*ND + t], s1);
            s2 = fmaf(sSh[k+2], WF[(size_t)(k+2)*ND + t], s2);
            s3 = fmaf(sSh[k+3], WF[(size_t)(k+3)*ND + t], s3);
        }
        sCB[t] = (s0 + s1) + (s2 + s3);
    }
    __syncthreads();

    int bm = blockIdx.x * 128;
    int arow = t >> 1, acol = (t & 1) * 4;
    int brow = t >> 5, bcol = (t & 31) * 4;
    int tx = t & 15, ty = t >> 4;
    float acc[8][8] = {};
    const float* Aptr = g_F1 + (size_t)(bm + arow) * F0D + acol;
    for (int k0 = 0; k0 < F0D; k0 += 8) {
        float4 av = *(const float4*)(Aptr + k0);
        float4 sc = *(const float4*)&sSC[k0 + acol];
        av.x *= sc.x; av.y *= sc.y; av.z *= sc.z; av.w *= sc.w;
        float4 bv = *(const float4*)(WF + (size_t)(k0 + brow) * ND + bcol);
        As[acol+0][arow] = av.x; As[acol+1][arow] = av.y;
        As[acol+2][arow] = av.z; As[acol+3][arow] = av.w;
        *(float4*)&Bs[brow][bcol] = bv;
        __syncthreads();
        #pragma unroll
        for (int kk = 0; kk < 8; kk++) {
            float ra[8], rb[8];
            *(float4*)(ra)   = *(float4*)&As[kk][ty*4];
            *(float4*)(ra+4) = *(float4*)&As[kk][64 + ty*4];
            *(float4*)(rb)   = *(float4*)&Bs[kk][tx*4];
            *(float4*)(rb+4) = *(float4*)&Bs[kk][64 + tx*4];
            #pragma unroll
            for (int i = 0; i < 8; i++)
                #pragma unroll
                for (int j = 0; j < 8; j++) acc[i][j] = fmaf(ra[i], rb[j], acc[i][j]);
        }
        __syncthreads();
    }
    float cS[8] = {};
    #pragma unroll
    for (int i = 0; i < 8; i++) {
        int r    = bm + ((i < 4) ? ty*4 + i : 64 + ty*4 + (i-4));
        int b    = r >> 9;
        int nloc = r & 511;
        float* orow = out + ((size_t)b * HROWS + 1 + nloc) * ND;
        float v4[8];
        #pragma unroll
        for (int jj = 0; jj < 8; jj++) {
            int c = (jj < 4) ? tx*4 + jj : 64 + tx*4 + (jj-4);
            float v = acc[i][jj] + sCB[c];
            v = (v > 0.0f) ? v : 0.01f * v;
            v4[jj] = v;
            cS[jj] += v;
        }
        *(float4*)(orow + tx*4)      = *(float4*)&v4[0];
        *(float4*)(orow + 64 + tx*4) = *(float4*)&v4[4];
    }
    #pragma unroll
    for (int jj = 0; jj < 8; jj++) {
        int cloc = (jj < 4) ? tx*4 + jj : 64 + tx*4 + (jj-4);
        redS[ty][cloc] = cS[jj];
    }
    __syncthreads();
    if (t < 128) {
        float s = 0.f;
        #pragma unroll
        for (int g = 0; g < 16; g++) s += redS[g][t];
        g_os[(size_t)blockIdx.x * ND + t] = s;
    }
}

// ---------------- depot row + per-batch mean from partials ----------------
__global__ void depmean_k(const float* __restrict__ depot, const float* __restrict__ Wd,
                          const float* __restrict__ bd, float* __restrict__ out) {
    int b = blockIdx.x, t = threadIdx.x;                   // 32 x 128
    float v = fmaf(depot[b*2+0], Wd[t], fmaf(depot[b*2+1], Wd[ND + t], bd[t]));
    out[(size_t)b * HROWS * ND + t] = v;
    float tot = v + g_os[(size_t)(4*b)*ND + t]   + g_os[(size_t)(4*b+1)*ND + t]
                  + g_os[(size_t)(4*b+2)*ND + t] + g_os[(size_t)(4*b+3)*ND + t];
    out[(size_t)BATCH * HROWS * ND + (size_t)b * ND + t] = tot * (1.0f / HROWS);
}

// ---------------- launch ----------------
extern "C" void kernel_launch(void* const* d_in, const int* in_sizes, int n_in,
                              void* d_out, int out_size) {
    const float* loc   = (const float*)d_in[0];
    const float* dl    = (const float*)d_in[1];
    const float* depot = (const float*)d_in[3];
    const float* Wi    = (const float*)d_in[4];
    const float* bi    = (const float*)d_in[5];
    const float* Wd    = (const float*)d_in[6];
    const float* bd    = (const float*)d_in[7];
    const float* Wg1   = (const float*)d_in[8];
    const float* bg1   = (const float*)d_in[9];
    const float* Wg2   = (const float*)d_in[10];
    const float* bg2   = (const float*)d_in[11];
    const float* Wg3   = (const float*)d_in[12];
    const float* bg3   = (const float*)d_in[13];
    const float* gamma = (const float*)d_in[14];
    const float* beta  = (const float*)d_in[15];
    const float* WF    = (const float*)d_in[16];
    const float* bF    = (const float*)d_in[17];
    float* out = (float*)d_out;

    cudaFuncSetAttribute(lprop_k, cudaFuncAttributeMaxDynamicSharedMemorySize, LPSM_FLOATS*4);

    init_k   <<<1, 64>>>();
    dlmax_k  <<<NN/256, 256>>>(dl);
    mono_k   <<<(NN+255)/256, 256>>>(loc, dl);
    a_k      <<<dim3(16, 16, BATCH), 256>>>();
    rbuild_k <<<dim3(64, 3), ND>>>(Wg1, Wg2, Wg3, Wi, bi);
    lprop_k  <<<dim3(4, BATCH), 256, LPSM_FLOATS*4>>>(0);
    lprop_k  <<<dim3(4, BATCH), 256, LPSM_FLOATS*4>>>(1);
    f1gemm_k <<<dim3(NN/128, 3), 256>>>(bg1, bg2, bg3, Wi, bi);
    fgemm_k  <<<NN/128, 256>>>(WF, bF, gamma, beta, out);
    depmean_k<<<BATCH, ND>>>(depot, Wd, bd, out);
}

// round 16
// speedup vs baseline: 1.0586x; 1.0273x over previous
#include <cuda_runtime.h>
#include <math.h>
#include <stdint.h>

#define BATCH 32
#define NPTS  512
#define NN    (BATCH*NPTS)     // 16384
#define ND    128
#define F0D   384
#define HROWS 513

// ---------------- scratch (device globals) ----------------
__device__ float g_L  [(size_t)BATCH*NPTS*NPTS];   // raw A
__device__ float g_U  [(size_t)NN*64];             // [M | LM | LLM | 0pad]
__device__ float g_Mt [(size_t)BATCH*20*NPTS];     // per batch [mono][point]
__device__ float g_LMt[(size_t)BATCH*20*NPTS];
__device__ float g_R  [(size_t)64*F0D];            // rows 60..63 zero
__device__ float g_F1 [(size_t)NN*F0D];
__device__ float g_X  [NN*3];
__device__ float g_deg[NN];
__device__ float g_ps [(size_t)128*F0D];           // BN partials per row-block
__device__ float g_pq [(size_t)128*F0D];
__device__ float g_os [(size_t)128*ND];            // fgemm per-block channel sums
__device__ unsigned g_dlmax_bits;
__device__ unsigned g_amax_bits;

// ---------------- small kernels (R12-proven) ----------------
__global__ void init_k() {
    if (threadIdx.x == 0) { g_dlmax_bits = 0u; g_amax_bits = 0u; }
}
__global__ void dlmax_k(const float* __restrict__ dl) {
    int i = blockIdx.x * blockDim.x + threadIdx.x;
    float v = dl[i];
    #pragma unroll
    for (int o = 16; o; o >>= 1) v = fmaxf(v, __shfl_xor_sync(0xffffffff, v, o));
    if ((threadIdx.x & 31) == 0) atomicMax(&g_dlmax_bits, __float_as_uint(v));
}
__global__ void mono_k(const float* __restrict__ loc, const float* __restrict__ dl) {
    int i = blockIdx.x * blockDim.x + threadIdx.x;
    if (i >= NN) return;
    float inv = 1.0f / __uint_as_float(g_dlmax_bits);
    float x = loc[i*2+0], y = loc[i*2+1], z = dl[i] * inv;
    g_X[i*3+0] = x; g_X[i*3+1] = y; g_X[i*3+2] = z;
    float m[20];
    m[0]=1.0f; m[1]=x; m[2]=y; m[3]=z;
    m[4]=x*x; m[5]=x*y; m[6]=x*z; m[7]=y*y; m[8]=y*z; m[9]=z*z;
    m[10]=m[4]*x; m[11]=m[4]*y; m[12]=m[4]*z; m[13]=x*m[7]; m[14]=m[5]*z;
    m[15]=x*m[9]; m[16]=m[7]*y; m[17]=m[7]*z; m[18]=y*m[9]; m[19]=m[9]*z;
    float* u = g_U + (size_t)i*64;
    #pragma unroll
    for (int p = 0; p < 20; p++) u[p] = m[p];
    u[60]=0.f; u[61]=0.f; u[62]=0.f; u[63]=0.f;
    int b = i >> 9, nl = i & 511;
    #pragma unroll
    for (int p = 0; p < 20; p++) g_Mt[(size_t)b*20*NPTS + p*NPTS + nl] = m[p];
}
__global__ void a_k() {
    int ti = blockIdx.y, tj = blockIdx.x;
    if (ti > tj) return;
    int b  = blockIdx.z;
    int i0 = ti * 32, j0 = tj * 32;
    __shared__ float Xi[32][3], Xj[32][3];
    __shared__ float T[32][33];
    int t = threadIdx.x;
    if (t < 96)       ((float*)Xi)[t]    = g_X[((size_t)b*NPTS + i0)*3 + t];
    else if (t < 192) ((float*)Xj)[t-96] = g_X[((size_t)b*NPTS + j0)*3 + (t-96)];
    __syncthreads();
    int tx = t & 31, ty = t >> 5;
    float xj0 = Xj[tx][0], xj1 = Xj[tx][1], xj2 = Xj[tx][2];
    float m = 0.0f;
    float* Ab = g_L + (size_t)b * NPTS * NPTS;
    #pragma unroll
    for (int r = 0; r < 4; r++) {
        int i = ty * 4 + r;
        float dx = Xi[i][0]-xj0, dy = Xi[i][1]-xj1, dz = Xi[i][2]-xj2;
        float d2 = dx*dx + dy*dy + dz*dz;
        float v  = (i0 + i == j0 + tx) ? 0.0f : rsqrtf(d2);
        Ab[(size_t)(i0+i)*NPTS + j0 + tx] = v;
        T[i][tx] = v;
        m = fmaxf(m, v);
    }
    #pragma unroll
    for (int o = 16; o; o >>= 1) m = fmaxf(m, __shfl_xor_sync(0xffffffff, m, o));
    __shared__ float wm[8];
    if (tx == 0) wm[ty] = m;
    __syncthreads();
    if (ti < tj) {
        #pragma unroll
        for (int r = 0; r < 4; r++) {
            int ip = ty * 4 + r;
            Ab[(size_t)(j0+ip)*NPTS + i0 + tx] = T[tx][ip];   // transposed mirror
        }
    }
    if (t == 0) {
        float mx = wm[0];
        #pragma unroll
        for (int w = 1; w < 8; w++) mx = fmaxf(mx, wm[w]);
        atomicMax(&g_amax_bits, __float_as_uint(mx));
    }
}

// ---------------- polynomial coefficient (power kb+1, monomial pm) ----------------
__device__ __forceinline__ float coefP(int kb, int pm, float a, float b, float c, float d) {
    if (kb == 0) {
        switch (pm) { case 0: return d; case 1: return a; case 2: return b; case 3: return c; }
        return 0.f;
    } else if (kb == 1) {
        switch (pm) {
            case 0: return d*d;     case 1: return 2.f*a*d; case 2: return 2.f*b*d;
            case 3: return 2.f*c*d; case 4: return a*a;     case 5: return 2.f*a*b;
            case 6: return 2.f*a*c; case 7: return b*b;     case 8: return 2.f*b*c;
            case 9: return c*c;
        }
        return 0.f;
    }
    switch (pm) {
        case 0:  return d*d*d;     case 1:  return 3.f*a*d*d; case 2:  return 3.f*b*d*d;
        case 3:  return 3.f*c*d*d; case 4:  return 3.f*a*a*d; case 5:  return 6.f*a*b*d;
        case 6:  return 6.f*a*c*d; case 7:  return 3.f*b*b*d; case 8:  return 6.f*b*c*d;
        case 9:  return 3.f*c*c*d; case 10: return a*a*a;     case 11: return 3.f*a*a*b;
        case 12: return 3.f*a*a*c; case 13: return 3.f*a*b*b; case 14: return 6.f*a*b*c;
        case 15: return 3.f*a*c*c; case 16: return b*b*b;     case 17: return 3.f*b*b*c;
        case 18: return 3.f*b*c*c; case 19: return c*c*c;
    }
    return 0.f;
}

__global__ void rbuild_k(const float* __restrict__ W1, const float* __restrict__ W2,
                         const float* __restrict__ W3, const float* __restrict__ Wi,
                         const float* __restrict__ bi) {
    int p  = blockIdx.x;           // 0..63
    int kb = blockIdx.y;           // 0..2
    int jj = threadIdx.x;          // 0..127
    if (p >= 60) { g_R[(size_t)p*F0D + kb*ND + jj] = 0.f; return; }
    __shared__ float sa[F0D], sb[F0D], sc_[F0D], sd[F0D];
    for (int j = jj; j < F0D; j += 128) {
        sa[j] = Wi[j]; sb[j] = Wi[F0D+j]; sc_[j] = Wi[2*F0D+j]; sd[j] = bi[j];
    }
    __syncthreads();
    int t = p / 20, pm = p % 20;
    const float* Wg = ((kb == 0) ? W1 : (kb == 1 ? W2 : W3)) + (size_t)t*F0D*ND + jj;
    float s0 = 0.f, s1 = 0.f, s2 = 0.f, s3 = 0.f;
    #pragma unroll 2
    for (int j = 0; j < F0D; j += 4) {
        s0 = fmaf(coefP(kb, pm, sa[j],   sb[j],   sc_[j],   sd[j]),   Wg[(size_t)j*ND],     s0);
        s1 = fmaf(coefP(kb, pm, sa[j+1], sb[j+1], sc_[j+1], sd[j+1]), Wg[(size_t)(j+1)*ND], s1);
        s2 = fmaf(coefP(kb, pm, sa[j+2], sb[j+2], sc_[j+2], sd[j+2]), Wg[(size_t)(j+2)*ND], s2);
        s3 = fmaf(coefP(kb, pm, sa[j+3], sb[j+3], sc_[j+3], sd[j+3]), Wg[(size_t)(j+3)*ND], s3);
    }
    g_R[(size_t)p*F0D + kb*ND + jj] = (s0 + s1) + (s2 + s3);
}

// ---------------- lprop: 2-row register blocking (regs ~70, occ up) ----------------
// mode 0: Mt -> U[20:40] + LMt + deg ; mode 1: LMt -> U[40:60]
__global__ void __launch_bounds__(256) lprop_k(int mode) {
    __shared__ float Ms[20*NPTS];          // 40 KB
    int b = blockIdx.y;
    const float* src = (mode ? g_LMt : g_Mt) + (size_t)b*20*NPTS;
    for (int i = threadIdx.x; i < 20*NPTS; i += 256) Ms[i] = src[i];
    __syncthreads();
    float inv = 1.0f / __uint_as_float(g_amax_bits);
    int wid = threadIdx.x >> 5, lane = threadIdx.x & 31;
    #pragma unroll 1
    for (int g = 0; g < 4; g++) {
        int il0 = blockIdx.x*64 + wid*8 + g*2;             // 2 consecutive rows
        const float* A0 = g_L + ((size_t)b*NPTS + il0)*NPTS;
        float acc[2][20];
        float rs[2] = {0.f, 0.f};
        #pragma unroll
        for (int r = 0; r < 2; r++)
            #pragma unroll
            for (int c = 0; c < 20; c++) acc[r][c] = 0.f;
        #pragma unroll 2
        for (int t = 0; t < 16; t++) {
            int idx = lane + 32*t;
            float a0 = A0[idx];
            float a1 = A0[NPTS + idx];
            rs[0] += a0; rs[1] += a1;
            #pragma unroll
            for (int c = 0; c < 20; c++) {
                float ms = Ms[c*NPTS + idx];
                acc[0][c] = fmaf(a0, ms, acc[0][c]);
                acc[1][c] = fmaf(a1, ms, acc[1][c]);
            }
        }
        #pragma unroll
        for (int r = 0; r < 2; r++) {
            #pragma unroll
            for (int o = 16; o; o >>= 1) rs[r] += __shfl_xor_sync(0xffffffff, rs[r], o);
            #pragma unroll
            for (int c = 0; c < 20; c++) {
                float v = acc[r][c];
                #pragma unroll
                for (int o = 16; o; o >>= 1) v += __shfl_xor_sync(0xffffffff, v, o);
                acc[r][c] = v;
            }
        }
        if (lane < 2) {                        // lane r handles row il0+r (warp-uniform values)
            int il = il0 + lane;
            float rsv = (lane == 0) ? rs[0] : rs[1];
            float deg;
            if (!mode) { deg = rsv * inv - 1.0f; g_deg[(size_t)b*NPTS + il] = deg; }
            else        deg = g_deg[(size_t)b*NPTS + il];
            float* u = g_U + ((size_t)b*NPTS + il)*64 + (mode ? 40 : 20);
            #pragma unroll
            for (int c = 0; c < 20; c++) {
                float av = (lane == 0) ? acc[0][c] : acc[1][c];
                float o = deg * Ms[c*NPTS + il] - av * inv;
                u[c] = o;
                if (!mode) g_LMt[(size_t)b*20*NPTS + c*NPTS + il] = o;
            }
        }
    }
}

// ---------------- F1 = leaky(U@R + bg) + F0(inline) ; epilogue: BN partials ----------------
__global__ void __launch_bounds__(256) f1gemm_k(
    const float* __restrict__ bg1, const float* __restrict__ bg2, const float* __restrict__ bg3,
    const float* __restrict__ Wi,  const float* __restrict__ bi)
{
    int bm = blockIdx.x * 128;
    int kb = blockIdx.y;
    const float* bg = (kb == 0) ? bg1 : (kb == 1 ? bg2 : bg3);
    __shared__ float As[8][128], Bs[8][128];
    __shared__ float sWa[128], sWb[128], sWc[128], sbi[128], sx[128], sy[128], sz[128];
    __shared__ float redS[16][128], redQ[16][128];
    int t = threadIdx.x;
    if (t < 128) {
        int c = kb*128 + t;
        sWa[t] = Wi[c]; sWb[t] = Wi[F0D+c]; sWc[t] = Wi[2*F0D+c]; sbi[t] = bi[c];
        int r = bm + t;
        sx[t] = g_X[(size_t)r*3]; sy[t] = g_X[(size_t)r*3+1]; sz[t] = g_X[(size_t)r*3+2];
    }
    int arow = t >> 1, acol = (t & 1) * 4;
    int brow = t >> 5, bcol = (t & 31) * 4;
    int tx = t & 15, ty = t >> 4;
    float acc[8][8] = {};
    const float* Aptr = g_U + (size_t)(bm + arow) * 64 + acol;
    const float* Bptr = g_R + (size_t)brow * F0D + kb * ND + bcol;
    __syncthreads();
    for (int k0 = 0; k0 < 64; k0 += 8) {
        float4 av = *(const float4*)(Aptr + k0);
        float4 bv = *(const float4*)(Bptr + (size_t)k0 * F0D);
        As[acol+0][arow] = av.x; As[acol+1][arow] = av.y;
        As[acol+2][arow] = av.z; As[acol+3][arow] = av.w;
        *(float4*)&Bs[brow][bcol] = bv;
        __syncthreads();
        #pragma unroll
        for (int kk = 0; kk < 8; kk++) {
            float ra[8], rb[8];
            *(float4*)(ra)   = *(float4*)&As[kk][ty*4];
            *(float4*)(ra+4) = *(float4*)&As[kk][64 + ty*4];
            *(float4*)(rb)   = *(float4*)&Bs[kk][tx*4];
            *(float4*)(rb+4) = *(float4*)&Bs[kk][64 + tx*4];
            #pragma unroll
            for (int i = 0; i < 8; i++)
                #pragma unroll
                for (int j = 0; j < 8; j++) acc[i][j] = fmaf(ra[i], rb[j], acc[i][j]);
        }
        __syncthreads();
    }
    float cS[8] = {}, cQ[8] = {};
    #pragma unroll
    for (int i = 0; i < 8; i++) {
        int rloc = (i < 4) ? ty*4 + i : 64 + ty*4 + (i-4);
        int r = bm + rloc;
        #pragma unroll
        for (int jj = 0; jj < 8; jj++) {
            int cloc = (jj < 4) ? tx*4 + jj : 64 + tx*4 + (jj-4);
            float v = acc[i][jj] + bg[cloc];
            v = (v > 0.0f) ? v : 0.01f * v;
            v += fmaf(sx[rloc], sWa[cloc],
                 fmaf(sy[rloc], sWb[cloc],
                 fmaf(sz[rloc], sWc[cloc], sbi[cloc])));
            g_F1[(size_t)r * F0D + kb * ND + cloc] = v;
            cS[jj] += v; cQ[jj] += v * v;
        }
    }
    #pragma unroll
    for (int jj = 0; jj < 8; jj++) {
        int cloc = (jj < 4) ? tx*4 + jj : 64 + tx*4 + (jj-4);
        redS[ty][cloc] = cS[jj]; redQ[ty][cloc] = cQ[jj];
    }
    __syncthreads();
    if (t < 128) {
        float s = 0.f, q = 0.f;
        #pragma unroll
        for (int g = 0; g < 16; g++) { s += redS[g][t]; q += redQ[g][t]; }
        g_ps[(size_t)blockIdx.x * F0D + kb * ND + t] = s;
        g_pq[(size_t)blockIdx.x * F0D + kb * ND + t] = q;
    }
}

// ---------------- final GEMM: BN finalize in prologue + g_os epilogue ----------------
__global__ void __launch_bounds__(256) fgemm_k(
    const float* __restrict__ WF, const float* __restrict__ bF,
    const float* __restrict__ gamma, const float* __restrict__ beta,
    float* __restrict__ out)
{
    __shared__ float As[8][128], Bs[8][128];
    __shared__ float sSC[F0D], sSh[F0D], sCB[ND];
    __shared__ float redS[16][128];
    int t = threadIdx.x;
    for (int c = t; c < F0D; c += 256) {
        float s0=0.f, s1=0.f, q0=0.f, q1=0.f;
        #pragma unroll 4
        for (int rb = 0; rb < 128; rb += 2) {
            s0 += g_ps[(size_t)rb*F0D + c];     q0 += g_pq[(size_t)rb*F0D + c];
            s1 += g_ps[(size_t)(rb+1)*F0D + c]; q1 += g_pq[(size_t)(rb+1)*F0D + c];
        }
        float s = s0 + s1, q = q0 + q1;
        float mu  = s * (1.0f / NN);
        float var = q * (1.0f / NN) - mu * mu;
        float sc  = gamma[c] * rsqrtf(var + 1e-5f);
        sSC[c] = sc; sSh[c] = beta[c] - mu * sc;
    }
    __syncthreads();
    if (t < ND) {
        float s0 = bF[t], s1 = 0.f, s2 = 0.f, s3 = 0.f;
        #pragma unroll 2
        for (int k = 0; k < F0D; k += 4) {
            s0 = fmaf(sSh[k],   WF[(size_t)k*ND + t],     s0);
            s1 = fmaf(sSh[k+1], WF[(size_t)(k+1)*ND + t], s1);
            s2 = fmaf(sSh[k+2], WF[(size_t)(k+2)*ND + t], s2);
            s3 = fmaf(sSh[k+3], WF[(size_t)(k+3)*ND + t], s3);
        }
        sCB[t] = (s0 + s1) + (s2 + s3);
    }
    __syncthreads();

    int bm = blockIdx.x * 128;
    int arow = t >> 1, acol = (t & 1) * 4;
    int brow = t >> 5, bcol = (t & 31) * 4;
    int tx = t & 15, ty = t >> 4;
    float acc[8][8] = {};
    const float* Aptr = g_F1 + (size_t)(bm + arow) * F0D + acol;
    for (int k0 = 0; k0 < F0D; k0 += 8) {
        float4 av = *(const float4*)(Aptr + k0);
        float4 sc = *(const float4*)&sSC[k0 + acol];
        av.x *= sc.x; av.y *= sc.y; av.z *= sc.z; av.w *= sc.w;
        float4 bv = *(const float4*)(WF + (size_t)(k0 + brow) * ND + bcol);
        As[acol+0][arow] = av.x; As[acol+1][arow] = av.y;
        As[acol+2][arow] = av.z; As[acol+3][arow] = av.w;
        *(float4*)&Bs[brow][bcol] = bv;
        __syncthreads();
        #pragma unroll
        for (int kk = 0; kk < 8; kk++) {
            float ra[8], rb[8];
            *(float4*)(ra)   = *(float4*)&As[kk][ty*4];
            *(float4*)(ra+4) = *(float4*)&As[kk][64 + ty*4];
            *(float4*)(rb)   = *(float4*)&Bs[kk][tx*4];
            *(float4*)(rb+4) = *(float4*)&Bs[kk][64 + tx*4];
            #pragma unroll
            for (int i = 0; i < 8; i++)
                #pragma unroll
                for (int j = 0; j < 8; j++) acc[i][j] = fmaf(ra[i], rb[j], acc[i][j]);
        }
        __syncthreads();
    }
    float cS[8] = {};
    #pragma unroll
    for (int i = 0; i < 8; i++) {
        int r    = bm + ((i < 4) ? ty*4 + i : 64 + ty*4 + (i-4));
        int b    = r >> 9;
        int nloc = r & 511;
        float* orow = out + ((size_t)b * HROWS + 1 + nloc) * ND;
        float v4[8];
        #pragma unroll
        for (int jj = 0; jj < 8; jj++) {
            int c = (jj < 4) ? tx*4 + jj : 64 + tx*4 + (jj-4);
            float v = acc[i][jj] + sCB[c];
            v = (v > 0.0f) ? v : 0.01f * v;
            v4[jj] = v;
            cS[jj] += v;
        }
        *(float4*)(orow + tx*4)      = *(float4*)&v4[0];
        *(float4*)(orow + 64 + tx*4) = *(float4*)&v4[4];
    }
    #pragma unroll
    for (int jj = 0; jj < 8; jj++) {
        int cloc = (jj < 4) ? tx*4 + jj : 64 + tx*4 + (jj-4);
        redS[ty][cloc] = cS[jj];
    }
    __syncthreads();
    if (t < 128) {
        float s = 0.f;
        #pragma unroll
        for (int g = 0; g < 16; g++) s += redS[g][t];
        g_os[(size_t)blockIdx.x * ND + t] = s;
    }
}

// ---------------- depot row + per-batch mean from partials ----------------
__global__ void depmean_k(const float* __restrict__ depot, const float* __restrict__ Wd,
                          const float* __restrict__ bd, float* __restrict__ out) {
    int b = blockIdx.x, t = threadIdx.x;                   // 32 x 128
    float v = fmaf(depot[b*2+0], Wd[t], fmaf(depot[b*2+1], Wd[ND + t], bd[t]));
    out[(size_t)b * HROWS * ND + t] = v;
    float tot = v + g_os[(size_t)(4*b)*ND + t]   + g_os[(size_t)(4*b+1)*ND + t]
                  + g_os[(size_t)(4*b+2)*ND + t] + g_os[(size_t)(4*b+3)*ND + t];
    out[(size_t)BATCH * HROWS * ND + (size_t)b * ND + t] = tot * (1.0f / HROWS);
}

// ---------------- launch ----------------
extern "C" void kernel_launch(void* const* d_in, const int* in_sizes, int n_in,
                              void* d_out, int out_size) {
    const float* loc   = (const float*)d_in[0];
    const float* dl    = (const float*)d_in[1];
    const float* depot = (const float*)d_in[3];
    const float* Wi    = (const float*)d_in[4];
    const float* bi    = (const float*)d_in[5];
    const float* Wd    = (const float*)d_in[6];
    const float* bd    = (const float*)d_in[7];
    const float* Wg1   = (const float*)d_in[8];
    const float* bg1   = (const float*)d_in[9];
    const float* Wg2   = (const float*)d_in[10];
    const float* bg2   = (const float*)d_in[11];
    const float* Wg3   = (const float*)d_in[12];
    const float* bg3   = (const float*)d_in[13];
    const float* gamma = (const float*)d_in[14];
    const float* beta  = (const float*)d_in[15];
    const float* WF    = (const float*)d_in[16];
    const float* bF    = (const float*)d_in[17];
    float* out = (float*)d_out;

    init_k   <<<1, 64>>>();
    dlmax_k  <<<NN/256, 256>>>(dl);
    mono_k   <<<(NN+255)/256, 256>>>(loc, dl);
    a_k      <<<dim3(16, 16, BATCH), 256>>>();
    rbuild_k <<<dim3(64, 3), ND>>>(Wg1, Wg2, Wg3, Wi, bi);
    lprop_k  <<<dim3(8, BATCH), 256>>>(0);
    lprop_k  <<<dim3(8, BATCH), 256>>>(1);
    f1gemm_k <<<dim3(NN/128, 3), 256>>>(bg1, bg2, bg3, Wi, bi);
    fgemm_k  <<<NN/128, 256>>>(WF, bF, gamma, beta, out);
    depmean_k<<<BATCH, ND>>>(depot, Wd, bd, out);
}

// round 17
// speedup vs baseline: 1.0616x; 1.0028x over previous
#include <cuda_runtime.h>
#include <math.h>
#include <stdint.h>

#define BATCH 32
#define NPTS  512
#define NN    (BATCH*NPTS)     // 16384
#define ND    128
#define F0D   384
#define HROWS 513

// ---------------- scratch (device globals) ----------------
__device__ float g_L  [(size_t)BATCH*NPTS*NPTS];   // raw A
__device__ float g_U  [(size_t)NN*64];             // [M | LM | LLM | 0pad]
__device__ float g_Mt [(size_t)BATCH*20*NPTS];     // per batch [mono][point]
__device__ float g_LMt[(size_t)BATCH*20*NPTS];
__device__ float g_R  [(size_t)64*F0D];            // rows 60..63 zero
__device__ float g_F1 [(size_t)NN*F0D];
__device__ float g_X  [NN*3];
__device__ float g_deg[NN];
__device__ float g_ps [(size_t)128*F0D];           // BN partials per row-block
__device__ float g_pq [(size_t)128*F0D];
__device__ float g_os [(size_t)128*ND];            // fgemm per-block channel sums
__device__ unsigned g_dlmax_bits;
__device__ unsigned g_amax_bits;

// ---------------- small kernels (proven) ----------------
__global__ void init_k() {
    if (threadIdx.x == 0) { g_dlmax_bits = 0u; g_amax_bits = 0u; }
}
__global__ void dlmax_k(const float* __restrict__ dl) {
    int i = blockIdx.x * blockDim.x + threadIdx.x;
    float v = dl[i];
    #pragma unroll
    for (int o = 16; o; o >>= 1) v = fmaxf(v, __shfl_xor_sync(0xffffffff, v, o));
    if ((threadIdx.x & 31) == 0) atomicMax(&g_dlmax_bits, __float_as_uint(v));
}
__global__ void mono_k(const float* __restrict__ loc, const float* __restrict__ dl) {
    int i = blockIdx.x * blockDim.x + threadIdx.x;
    if (i >= NN) return;
    float inv = 1.0f / __uint_as_float(g_dlmax_bits);
    float x = loc[i*2+0], y = loc[i*2+1], z = dl[i] * inv;
    g_X[i*3+0] = x; g_X[i*3+1] = y; g_X[i*3+2] = z;
    float m[20];
    m[0]=1.0f; m[1]=x; m[2]=y; m[3]=z;
    m[4]=x*x; m[5]=x*y; m[6]=x*z; m[7]=y*y; m[8]=y*z; m[9]=z*z;
    m[10]=m[4]*x; m[11]=m[4]*y; m[12]=m[4]*z; m[13]=x*m[7]; m[14]=m[5]*z;
    m[15]=x*m[9]; m[16]=m[7]*y; m[17]=m[7]*z; m[18]=y*m[9]; m[19]=m[9]*z;
    float* u = g_U + (size_t)i*64;
    #pragma unroll
    for (int p = 0; p < 20; p++) u[p] = m[p];
    u[60]=0.f; u[61]=0.f; u[62]=0.f; u[63]=0.f;
    int b = i >> 9, nl = i & 511;
    #pragma unroll
    for (int p = 0; p < 20; p++) g_Mt[(size_t)b*20*NPTS + p*NPTS + nl] = m[p];
}
__global__ void a_k() {
    int ti = blockIdx.y, tj = blockIdx.x;
    if (ti > tj) return;
    int b  = blockIdx.z;
    int i0 = ti * 32, j0 = tj * 32;
    __shared__ float Xi[32][3], Xj[32][3];
    __shared__ float T[32][33];
    int t = threadIdx.x;
    if (t < 96)       ((float*)Xi)[t]    = g_X[((size_t)b*NPTS + i0)*3 + t];
    else if (t < 192) ((float*)Xj)[t-96] = g_X[((size_t)b*NPTS + j0)*3 + (t-96)];
    __syncthreads();
    int tx = t & 31, ty = t >> 5;
    float xj0 = Xj[tx][0], xj1 = Xj[tx][1], xj2 = Xj[tx][2];
    float m = 0.0f;
    float* Ab = g_L + (size_t)b * NPTS * NPTS;
    #pragma unroll
    for (int r = 0; r < 4; r++) {
        int i = ty * 4 + r;
        float dx = Xi[i][0]-xj0, dy = Xi[i][1]-xj1, dz = Xi[i][2]-xj2;
        float d2 = dx*dx + dy*dy + dz*dz;
        float v  = (i0 + i == j0 + tx) ? 0.0f : rsqrtf(d2);
        Ab[(size_t)(i0+i)*NPTS + j0 + tx] = v;
        T[i][tx] = v;
        m = fmaxf(m, v);
    }
    #pragma unroll
    for (int o = 16; o; o >>= 1) m = fmaxf(m, __shfl_xor_sync(0xffffffff, m, o));
    __shared__ float wm[8];
    if (tx == 0) wm[ty] = m;
    __syncthreads();
    if (ti < tj) {
        #pragma unroll
        for (int r = 0; r < 4; r++) {
            int ip = ty * 4 + r;
            Ab[(size_t)(j0+ip)*NPTS + i0 + tx] = T[tx][ip];   // transposed mirror
        }
    }
    if (t == 0) {
        float mx = wm[0];
        #pragma unroll
        for (int w = 1; w < 8; w++) mx = fmaxf(mx, wm[w]);
        atomicMax(&g_amax_bits, __float_as_uint(mx));
    }
}

// ---------------- polynomial coefficient (power kb+1, monomial pm) ----------------
__device__ __forceinline__ float coefP(int kb, int pm, float a, float b, float c, float d) {
    if (kb == 0) {
        switch (pm) { case 0: return d; case 1: return a; case 2: return b; case 3: return c; }
        return 0.f;
    } else if (kb == 1) {
        switch (pm) {
            case 0: return d*d;     case 1: return 2.f*a*d; case 2: return 2.f*b*d;
            case 3: return 2.f*c*d; case 4: return a*a;     case 5: return 2.f*a*b;
            case 6: return 2.f*a*c; case 7: return b*b;     case 8: return 2.f*b*c;
            case 9: return c*c;
        }
        return 0.f;
    }
    switch (pm) {
        case 0:  return d*d*d;     case 1:  return 3.f*a*d*d; case 2:  return 3.f*b*d*d;
        case 3:  return 3.f*c*d*d; case 4:  return 3.f*a*a*d; case 5:  return 6.f*a*b*d;
        case 6:  return 6.f*a*c*d; case 7:  return 3.f*b*b*d; case 8:  return 6.f*b*c*d;
        case 9:  return 3.f*c*c*d; case 10: return a*a*a;     case 11: return 3.f*a*a*b;
        case 12: return 3.f*a*a*c; case 13: return 3.f*a*b*b; case 14: return 6.f*a*b*c;
        case 15: return 3.f*a*c*c; case 16: return b*b*b;     case 17: return 3.f*b*b*c;
        case 18: return 3.f*b*c*c; case 19: return c*c*c;
    }
    return 0.f;
}

__global__ void rbuild_k(const float* __restrict__ W1, const float* __restrict__ W2,
                         const float* __restrict__ W3, const float* __restrict__ Wi,
                         const float* __restrict__ bi) {
    int p  = blockIdx.x;           // 0..63
    int kb = blockIdx.y;           // 0..2
    int jj = threadIdx.x;          // 0..127
    if (p >= 60) { g_R[(size_t)p*F0D + kb*ND + jj] = 0.f; return; }
    __shared__ float sa[F0D], sb[F0D], sc_[F0D], sd[F0D];
    for (int j = jj; j < F0D; j += 128) {
        sa[j] = Wi[j]; sb[j] = Wi[F0D+j]; sc_[j] = Wi[2*F0D+j]; sd[j] = bi[j];
    }
    __syncthreads();
    int t = p / 20, pm = p % 20;
    const float* Wg = ((kb == 0) ? W1 : (kb == 1 ? W2 : W3)) + (size_t)t*F0D*ND + jj;
    float s0 = 0.f, s1 = 0.f, s2 = 0.f, s3 = 0.f;
    #pragma unroll 2
    for (int j = 0; j < F0D; j += 4) {
        s0 = fmaf(coefP(kb, pm, sa[j],   sb[j],   sc_[j],   sd[j]),   Wg[(size_t)j*ND],     s0);
        s1 = fmaf(coefP(kb, pm, sa[j+1], sb[j+1], sc_[j+1], sd[j+1]), Wg[(size_t)(j+1)*ND], s1);
        s2 = fmaf(coefP(kb, pm, sa[j+2], sb[j+2], sc_[j+2], sd[j+2]), Wg[(size_t)(j+2)*ND], s2);
        s3 = fmaf(coefP(kb, pm, sa[j+3], sb[j+3], sc_[j+3], sd[j+3]), Wg[(size_t)(j+3)*ND], s3);
    }
    g_R[(size_t)p*F0D + kb*ND + jj] = (s0 + s1) + (s2 + s3);
}

// ---------------- lprop: 2-row blocking, float4 LDG + float4 LDS ----------------
// mode 0: Mt -> U[20:40] + LMt + deg ; mode 1: LMt -> U[40:60]
__global__ void __launch_bounds__(256) lprop_k(int mode) {
    __shared__ float4 Ms4[20*128];         // 40 KB, [c][k4]
    float* Msf = (float*)Ms4;
    int b = blockIdx.y;
    const float4* src = (const float4*)((mode ? g_LMt : g_Mt) + (size_t)b*20*NPTS);
    for (int i = threadIdx.x; i < 20*128; i += 256) Ms4[i] = src[i];
    __syncthreads();
    float inv = 1.0f / __uint_as_float(g_amax_bits);
    int wid = threadIdx.x >> 5, lane = threadIdx.x & 31;
    #pragma unroll 1
    for (int g = 0; g < 4; g++) {
        int il0 = blockIdx.x*64 + wid*8 + g*2;             // 2 consecutive rows
        const float4* A0 = (const float4*)(g_L + ((size_t)b*NPTS + il0)*NPTS);
        const float4* A1 = A0 + 128;
        float acc0[20], acc1[20];
        #pragma unroll
        for (int c = 0; c < 20; c++) { acc0[c] = 0.f; acc1[c] = 0.f; }
        float rs0 = 0.f, rs1 = 0.f;
        #pragma unroll 2
        for (int t4 = 0; t4 < 4; t4++) {
            int idx = lane + 32*t4;                        // float4 index 0..127
            float4 a0 = A0[idx];
            float4 a1 = A1[idx];
            rs0 += (a0.x + a0.y) + (a0.z + a0.w);
            rs1 += (a1.x + a1.y) + (a1.z + a1.w);
            #pragma unroll
            for (int c = 0; c < 20; c++) {
                float4 m = Ms4[c*128 + idx];
                acc0[c] = fmaf(a0.x, m.x, acc0[c]);
                acc0[c] = fmaf(a0.y, m.y, acc0[c]);
                acc0[c] = fmaf(a0.z, m.z, acc0[c]);
                acc0[c] = fmaf(a0.w, m.w, acc0[c]);
                acc1[c] = fmaf(a1.x, m.x, acc1[c]);
                acc1[c] = fmaf(a1.y, m.y, acc1[c]);
                acc1[c] = fmaf(a1.z, m.z, acc1[c]);
                acc1[c] = fmaf(a1.w, m.w, acc1[c]);
            }
        }
        #pragma unroll
        for (int o = 16; o; o >>= 1) rs0 += __shfl_xor_sync(0xffffffff, rs0, o);
        #pragma unroll
        for (int o = 16; o; o >>= 1) rs1 += __shfl_xor_sync(0xffffffff, rs1, o);
        #pragma unroll
        for (int c = 0; c < 20; c++) {
            float v0 = acc0[c], v1 = acc1[c];
            #pragma unroll
            for (int o = 16; o; o >>= 1) {
                v0 += __shfl_xor_sync(0xffffffff, v0, o);
                v1 += __shfl_xor_sync(0xffffffff, v1, o);
            }
            acc0[c] = v0; acc1[c] = v1;
        }
        if (lane < 2) {                        // lane r handles row il0+r (warp-uniform values)
            int il = il0 + lane;
            float rsv = (lane == 0) ? rs0 : rs1;
            float deg;
            if (!mode) { deg = rsv * inv - 1.0f; g_deg[(size_t)b*NPTS + il] = deg; }
            else        deg = g_deg[(size_t)b*NPTS + il];
            float* u = g_U + ((size_t)b*NPTS + il)*64 + (mode ? 40 : 20);
            #pragma unroll
            for (int c = 0; c < 20; c++) {
                float av = (lane == 0) ? acc0[c] : acc1[c];
                float o = deg * Msf[c*NPTS + il] - av * inv;
                u[c] = o;
                if (!mode) g_LMt[(size_t)b*20*NPTS + c*NPTS + il] = o;
            }
        }
    }
}

// ---------------- F1 = leaky(U@R + bg) + F0(inline) ; epilogue: BN partials ----------------
__global__ void __launch_bounds__(256) f1gemm_k(
    const float* __restrict__ bg1, const float* __restrict__ bg2, const float* __restrict__ bg3,
    const float* __restrict__ Wi,  const float* __restrict__ bi)
{
    int bm = blockIdx.x * 128;
    int kb = blockIdx.y;
    const float* bg = (kb == 0) ? bg1 : (kb == 1 ? bg2 : bg3);
    __shared__ float As[8][128], Bs[8][128];
    __shared__ float sWa[128], sWb[128], sWc[128], sbi[128], sx[128], sy[128], sz[128];
    __shared__ float redS[16][128], redQ[16][128];
    int t = threadIdx.x;
    if (t < 128) {
        int c = kb*128 + t;
        sWa[t] = Wi[c]; sWb[t] = Wi[F0D+c]; sWc[t] = Wi[2*F0D+c]; sbi[t] = bi[c];
        int r = bm + t;
        sx[t] = g_X[(size_t)r*3]; sy[t] = g_X[(size_t)r*3+1]; sz[t] = g_X[(size_t)r*3+2];
    }
    int arow = t >> 1, acol = (t & 1) * 4;
    int brow = t >> 5, bcol = (t & 31) * 4;
    int tx = t & 15, ty = t >> 4;
    float acc[8][8] = {};
    const float* Aptr = g_U + (size_t)(bm + arow) * 64 + acol;
    const float* Bptr = g_R + (size_t)brow * F0D + kb * ND + bcol;
    __syncthreads();
    for (int k0 = 0; k0 < 64; k0 += 8) {
        float4 av = *(const float4*)(Aptr + k0);
        float4 bv = *(const float4*)(Bptr + (size_t)k0 * F0D);
        As[acol+0][arow] = av.x; As[acol+1][arow] = av.y;
        As[acol+2][arow] = av.z; As[acol+3][arow] = av.w;
        *(float4*)&Bs[brow][bcol] = bv;
        __syncthreads();
        #pragma unroll
        for (int kk = 0; kk < 8; kk++) {
            float ra[8], rb[8];
            *(float4*)(ra)   = *(float4*)&As[kk][ty*4];
            *(float4*)(ra+4) = *(float4*)&As[kk][64 + ty*4];
            *(float4*)(rb)   = *(float4*)&Bs[kk][tx*4];
            *(float4*)(rb+4) = *(float4*)&Bs[kk][64 + tx*4];
            #pragma unroll
            for (int i = 0; i < 8; i++)
                #pragma unroll
                for (int j = 0; j < 8; j++) acc[i][j] = fmaf(ra[i], rb[j], acc[i][j]);
        }
        __syncthreads();
    }
    float cS[8] = {}, cQ[8] = {};
    #pragma unroll
    for (int i = 0; i < 8; i++) {
        int rloc = (i < 4) ? ty*4 + i : 64 + ty*4 + (i-4);
        int r = bm + rloc;
        #pragma unroll
        for (int jj = 0; jj < 8; jj++) {
            int cloc = (jj < 4) ? tx*4 + jj : 64 + tx*4 + (jj-4);
            float v = acc[i][jj] + bg[cloc];
            v = (v > 0.0f) ? v : 0.01f * v;
            v += fmaf(sx[rloc], sWa[cloc],
                 fmaf(sy[rloc], sWb[cloc],
                 fmaf(sz[rloc], sWc[cloc], sbi[cloc])));
            g_F1[(size_t)r * F0D + kb * ND + cloc] = v;
            cS[jj] += v; cQ[jj] += v * v;
        }
    }
    #pragma unroll
    for (int jj = 0; jj < 8; jj++) {
        int cloc = (jj < 4) ? tx*4 + jj : 64 + tx*4 + (jj-4);
        redS[ty][cloc] = cS[jj]; redQ[ty][cloc] = cQ[jj];
    }
    __syncthreads();
    if (t < 128) {
        float s = 0.f, q = 0.f;
        #pragma unroll
        for (int g = 0; g < 16; g++) { s += redS[g][t]; q += redQ[g][t]; }
        g_ps[(size_t)blockIdx.x * F0D + kb * ND + t] = s;
        g_pq[(size_t)blockIdx.x * F0D + kb * ND + t] = q;
    }
}

// ---------------- final GEMM: BN finalize in prologue + g_os epilogue ----------------
__global__ void __launch_bounds__(256) fgemm_k(
    const float* __restrict__ WF, const float* __restrict__ bF,
    const float* __restrict__ gamma, const float* __restrict__ beta,
    float* __restrict__ out)
{
    __shared__ float As[8][128], Bs[8][128];
    __shared__ float sSC[F0D], sSh[F0D], sCB[ND];
    __shared__ float redS[16][128];
    int t = threadIdx.x;
    for (int c = t; c < F0D; c += 256) {
        float s0=0.f, s1=0.f, q0=0.f, q1=0.f;
        #pragma unroll 4
        for (int rb = 0; rb < 128; rb += 2) {
            s0 += g_ps[(size_t)rb*F0D + c];     q0 += g_pq[(size_t)rb*F0D + c];
            s1 += g_ps[(size_t)(rb+1)*F0D + c]; q1 += g_pq[(size_t)(rb+1)*F0D + c];
        }
        float s = s0 + s1, q = q0 + q1;
        float mu  = s * (1.0f / NN);
        float var = q * (1.0f / NN) - mu * mu;
        float sc  = gamma[c] * rsqrtf(var + 1e-5f);
        sSC[c] = sc; sSh[c] = beta[c] - mu * sc;
    }
    __syncthreads();
    if (t < ND) {
        float s0 = bF[t], s1 = 0.f, s2 = 0.f, s3 = 0.f;
        #pragma unroll 2
        for (int k = 0; k < F0D; k += 4) {
            s0 = fmaf(sSh[k],   WF[(size_t)k*ND + t],     s0);
            s1 = fmaf(sSh[k+1], WF[(size_t)(k+1)*ND + t], s1);
            s2 = fmaf(sSh[k+2], WF[(size_t)(k+2)*ND + t], s2);
            s3 = fmaf(sSh[k+3], WF[(size_t)(k+3)*ND + t], s3);
        }
        sCB[t] = (s0 + s1) + (s2 + s3);
    }
    __syncthreads();

    int bm = blockIdx.x * 128;
    int arow = t >> 1, acol = (t & 1) * 4;
    int brow = t >> 5, bcol = (t & 31) * 4;
    int tx = t & 15, ty = t >> 4;
    float acc[8][8] = {};
    const float* Aptr = g_F1 + (size_t)(bm + arow) * F0D + acol;
    for (int k0 = 0; k0 < F0D; k0 += 8) {
        float4 av = *(const float4*)(Aptr + k0);
        float4 sc = *(const float4*)&sSC[k0 + acol];
        av.x *= sc.x; av.y *= sc.y; av.z *= sc.z; av.w *= sc.w;
        float4 bv = *(const float4*)(WF + (size_t)(k0 + brow) * ND + bcol);
        As[acol+0][arow] = av.x; As[acol+1][arow] = av.y;
        As[acol+2][arow] = av.z; As[acol+3][arow] = av.w;
        *(float4*)&Bs[brow][bcol] = bv;
        __syncthreads();
        #pragma unroll
        for (int kk = 0; kk < 8; kk++) {
            float ra[8], rb[8];
            *(float4*)(ra)   = *(float4*)&As[kk][ty*4];
            *(float4*)(ra+4) = *(float4*)&As[kk][64 + ty*4];
            *(float4*)(rb)   = *(float4*)&Bs[kk][tx*4];
            *(float4*)(rb+4) = *(float4*)&Bs[kk][64 + tx*4];
            #pragma unroll
            for (int i = 0; i < 8; i++)
                #pragma unroll
                for (int j = 0; j < 8; j++) acc[i][j] = fmaf(ra[i], rb[j], acc[i][j]);
        }
        __syncthreads();
    }
    float cS[8] = {};
    #pragma unroll
    for (int i = 0; i < 8; i++) {
        int r    = bm + ((i < 4) ? ty*4 + i : 64 + ty*4 + (i-4));
        int b    = r >> 9;
        int nloc = r & 511;
        float* orow = out + ((size_t)b * HROWS + 1 + nloc) * ND;
        float v4[8];
        #pragma unroll
        for (int jj = 0; jj < 8; jj++) {
            int c = (jj < 4) ? tx*4 + jj : 64 + tx*4 + (jj-4);
            float v = acc[i][jj] + sCB[c];
            v = (v > 0.0f) ? v : 0.01f * v;
            v4[jj] = v;
            cS[jj] += v;
        }
        *(float4*)(orow + tx*4)      = *(float4*)&v4[0];
        *(float4*)(orow + 64 + tx*4) = *(float4*)&v4[4];
    }
    #pragma unroll
    for (int jj = 0; jj < 8; jj++) {
        int cloc = (jj < 4) ? tx*4 + jj : 64 + tx*4 + (jj-4);
        redS[ty][cloc] = cS[jj];
    }
    __syncthreads();
    if (t < 128) {
        float s = 0.f;
        #pragma unroll
        for (int g = 0; g < 16; g++) s += redS[g][t];
        g_os[(size_t)blockIdx.x * ND + t] = s;
    }
}

// ---------------- depot row + per-batch mean from partials ----------------
__global__ void depmean_k(const float* __restrict__ depot, const float* __restrict__ Wd,
                          const float* __restrict__ bd, float* __restrict__ out) {
    int b = blockIdx.x, t = threadIdx.x;                   // 32 x 128
    float v = fmaf(depot[b*2+0], Wd[t], fmaf(depot[b*2+1], Wd[ND + t], bd[t]));
    out[(size_t)b * HROWS * ND + t] = v;
    float tot = v + g_os[(size_t)(4*b)*ND + t]   + g_os[(size_t)(4*b+1)*ND + t]
                  + g_os[(size_t)(4*b+2)*ND + t] + g_os[(size_t)(4*b+3)*ND + t];
    out[(size_t)BATCH * HROWS * ND + (size_t)b * ND + t] = tot * (1.0f / HROWS);
}

// ---------------- launch ----------------
extern "C" void kernel_launch(void* const* d_in, const int* in_sizes, int n_in,
                              void* d_out, int out_size) {
    const float* loc   = (const float*)d_in[0];
    const float* dl    = (const float*)d_in[1];
    const float* depot = (const float*)d_in[3];
    const float* Wi    = (const float*)d_in[4];
    const float* bi    = (const float*)d_in[5];
    const float* Wd    = (const float*)d_in[6];
    const float* bd    = (const float*)d_in[7];
    const float* Wg1   = (const float*)d_in[8];
    const float* bg1   = (const float*)d_in[9];
    const float* Wg2   = (const float*)d_in[10];
    const float* bg2   = (const float*)d_in[11];
    const float* Wg3   = (const float*)d_in[12];
    const float* bg3   = (const float*)d_in[13];
    const float* gamma = (const float*)d_in[14];
    const float* beta  = (const float*)d_in[15];
    const float* WF    = (const float*)d_in[16];
    const float* bF    = (const float*)d_in[17];
    float* out = (float*)d_out;

    init_k   <<<1, 64>>>();
    dlmax_k  <<<NN/256, 256>>>(dl);
    mono_k   <<<(NN+255)/256, 256>>>(loc, dl);
    a_k      <<<dim3(16, 16, BATCH), 256>>>();
    rbuild_k <<<dim3(64, 3), ND>>>(Wg1, Wg2, Wg3, Wi, bi);
    lprop_k  <<<dim3(8, BATCH), 256>>>(0);
    lprop_k  <<<dim3(8, BATCH), 256>>>(1);
    f1gemm_k <<<dim3(NN/128, 3), 256>>>(bg1, bg2, bg3, Wi, bi);
    fgemm_k  <<<NN/128, 256>>>(WF, bF, gamma, beta, out);
    depmean_k<<<BATCH, ND>>>(depot, Wd, bd, out);
}